// round 2
// baseline (speedup 1.0000x reference)
#include <cuda_runtime.h>
#include <cstdint>
#include <math.h>

#define SEQ 2048
#define HID 2048
#define NB  2
#define NH  16
#define HD  128
#define BH  (NB*NH)          // 32
#define MTOT (NB*SEQ)        // 4096
#define NEGMASK (-(1<<20))

// ---------------- device scratch (no allocation allowed) ----------------
__device__ int g_flag[9];                          // per-input dtype: 0=int32,1=float32,2=int8
__device__ unsigned g_x4[MTOT * (HID/4)];          // x packed u8x4   [4096][512]
__device__ signed char g_w8[4 * HID * HID];        // canonical s8 weights q,k,v,o [k][n]
__device__ int g_b32[4 * HID];                     // canonical i32 biases
__device__ unsigned g_wt[3 * HID * (HID/4)];       // wq/wk/wv transposed+packed [n][k/4]
__device__ int g_q[BH * SEQ * HD];                 // [bh][s][d]
__device__ int g_k[BH * SEQ * HD];
__device__ int g_v[BH * SEQ * HD];
__device__ int g_ctx[MTOT * HID];                  // [b*s][h*128+d]

__device__ __forceinline__ int dp4a_us(unsigned a, unsigned b, int c) {
    int d;
    asm("dp4a.u32.s32 %0, %1, %2, %3;" : "=r"(d) : "r"(a), "r"(b), "r"(c));
    return d;
}

// ---------------- dtype detection ----------------
// Classify a nonzero 32-bit word given values are small ints (|v| <= 520):
//  0: looks like int32 small value   1: looks like float32 integer value   2: packed bytes
__device__ __forceinline__ int classify_word(unsigned w) {
    if (w == 0u) return -1;
    int iv = (int)w;
    if (iv >= -520 && iv <= 520) return 0;
    float f = __int_as_float(w);
    if (isfinite(f) && fabsf(f) <= 520.0f && f != 0.0f && f == rintf(f)) return 1;
    return 2;
}

__global__ void detect_kernel(const void* p0, const void* p1, const void* p2,
                              const void* p3, const void* p4, const void* p5,
                              const void* p6, const void* p7, const void* p8) {
    const void* ptrs[9] = {p0,p1,p2,p3,p4,p5,p6,p7,p8};
    int b = blockIdx.x;
    const unsigned* w = (const unsigned*)ptrs[b];
    // bias inputs (idx 2,4,6,8) have >=2048 elements -> >=2048 bytes even if int8;
    // limit to 512 words (2KB). Others >= 4MB: 1024 words safe.
    int n = (b == 2 || b == 4 || b == 6 || b == 8) ? 512 : 1024;
    __shared__ int votes[3];
    if (threadIdx.x < 3) votes[threadIdx.x] = 0;
    __syncthreads();
    int local[3] = {0,0,0};
    for (int i = threadIdx.x; i < n; i += blockDim.x) {
        int c = classify_word(w[i]);
        if (c >= 0) local[c]++;
    }
    for (int c = 0; c < 3; c++) if (local[c]) atomicAdd(&votes[c], local[c]);
    __syncthreads();
    if (threadIdx.x == 0) {
        int best = 0;
        if (votes[1] > votes[best]) best = 1;
        if (votes[2] > votes[best]) best = 2;
        g_flag[b] = best;
    }
}

// ---------------- canonicalize x -> u8x4 words ----------------
__global__ void conv_x_kernel(const void* __restrict__ xp) {
    int i = blockIdx.x * blockDim.x + threadIdx.x;
    if (i >= MTOT * (HID/4)) return;
    int flag = g_flag[0];
    unsigned a, b, c, d;
    if (flag == 1) {
        float4 v = reinterpret_cast<const float4*>(xp)[i];
        a = (unsigned)(int)v.x; b = (unsigned)(int)v.y;
        c = (unsigned)(int)v.z; d = (unsigned)(int)v.w;
    } else {
        int4 v = reinterpret_cast<const int4*>(xp)[i];
        a = (unsigned)v.x; b = (unsigned)v.y; c = (unsigned)v.z; d = (unsigned)v.w;
    }
    g_x4[i] = (a & 255u) | ((b & 255u) << 8) | ((c & 255u) << 16) | ((d & 255u) << 24);
}

// ---------------- canonicalize weight -> s8 [k][n] ----------------
__global__ void conv_w_kernel(const void* __restrict__ wp, int slot, int flagidx) {
    int i = blockIdx.x * blockDim.x + threadIdx.x;
    if (i >= HID * HID / 4) return;
    int flag = g_flag[flagidx];
    unsigned* dst = reinterpret_cast<unsigned*>(g_w8 + (size_t)slot * HID * HID);
    unsigned packed;
    if (flag == 2) {
        packed = reinterpret_cast<const unsigned*>(wp)[i];
    } else if (flag == 1) {
        float4 v = reinterpret_cast<const float4*>(wp)[i];
        packed = ((unsigned)(int)v.x & 255u) | (((unsigned)(int)v.y & 255u) << 8) |
                 (((unsigned)(int)v.z & 255u) << 16) | (((unsigned)(int)v.w & 255u) << 24);
    } else {
        int4 v = reinterpret_cast<const int4*>(wp)[i];
        packed = ((unsigned)v.x & 255u) | (((unsigned)v.y & 255u) << 8) |
                 (((unsigned)v.z & 255u) << 16) | (((unsigned)v.w & 255u) << 24);
    }
    dst[i] = packed;
}

// ---------------- canonicalize bias -> i32 ----------------
__global__ void conv_b_kernel(const void* __restrict__ bp, int slot, int flagidx) {
    int i = blockIdx.x * blockDim.x + threadIdx.x;
    if (i >= HID) return;
    int flag = g_flag[flagidx];
    int v;
    if (flag == 1) v = (int)reinterpret_cast<const float*>(bp)[i];
    else           v = reinterpret_cast<const int*>(bp)[i];
    g_b32[slot * HID + i] = v;
}

// ---------------- transpose+pack weight: s8 [k][n] -> wt[n][k/4] ----------------
__global__ void pack_w_kernel(int slot) {
    int i = blockIdx.x * blockDim.x + threadIdx.x;
    if (i < HID * (HID/4)) {
        const signed char* w = g_w8 + (size_t)slot * HID * HID;
        int kw = i >> 11;          // 0..511
        int n  = i & (HID-1);      // 0..2047
        unsigned b0 = (unsigned char)w[(4*kw+0)*HID + n];
        unsigned b1 = (unsigned char)w[(4*kw+1)*HID + n];
        unsigned b2 = (unsigned char)w[(4*kw+2)*HID + n];
        unsigned b3 = (unsigned char)w[(4*kw+3)*HID + n];
        g_wt[slot * (HID*(HID/4)) + n*(HID/4) + kw] = b0 | (b1<<8) | (b2<<16) | (b3<<24);
    }
}

// ---------------- QKV projection GEMM (dp4a, exact) ----------------
__global__ __launch_bounds__(256) void proj_gemm_kernel(int slot) {
    __shared__ unsigned As[16][128];
    __shared__ unsigned Bs[16][128];
    const unsigned* W4 = g_wt + slot * (HID*(HID/4));
    const int* bias = g_b32 + slot * HID;
    int* outp = (slot == 0) ? g_q : (slot == 1) ? g_k : g_v;

    int bn = blockIdx.x;   // 0..15
    int bm = blockIdx.y;   // 0..31
    int t = threadIdx.x;
    int m0 = (t >> 4) * 8;
    int n0 = (t & 15) * 8;
    int lrow = t >> 1;
    int lk8 = (t & 1) * 8;

    int acc[8][8];
#pragma unroll
    for (int i = 0; i < 8; i++)
#pragma unroll
        for (int j = 0; j < 8; j++) acc[i][j] = 0;

    for (int kt = 0; kt < HID/4; kt += 16) {
#pragma unroll
        for (int j = 0; j < 8; j++)
            As[lk8 + j][lrow] = g_x4[(bm*128 + lrow)*(HID/4) + kt + lk8 + j];
#pragma unroll
        for (int j = 0; j < 8; j++)
            Bs[lk8 + j][lrow] = W4[(bn*128 + lrow)*(HID/4) + kt + lk8 + j];
        __syncthreads();
#pragma unroll
        for (int kw = 0; kw < 16; kw++) {
            unsigned a[8], b[8];
#pragma unroll
            for (int i = 0; i < 8; i++) a[i] = As[kw][m0 + i];
#pragma unroll
            for (int j = 0; j < 8; j++) b[j] = Bs[kw][n0 + j];
#pragma unroll
            for (int i = 0; i < 8; i++)
#pragma unroll
                for (int j = 0; j < 8; j++)
                    acc[i][j] = dp4a_us(a[i], b[j], acc[i][j]);
        }
        __syncthreads();
    }
#pragma unroll
    for (int i = 0; i < 8; i++) {
        int m = bm*128 + m0 + i;
        int b = m >> 11, s = m & (SEQ-1);
#pragma unroll
        for (int j = 0; j < 8; j++) {
            int n = bn*128 + n0 + j;
            int val = (acc[i][j] + bias[n]) >> 6;
            int h = n >> 7, d = n & (HD-1);
            outp[((size_t)(b*NH + h)*SEQ + s)*HD + d] = val;
        }
    }
}

// ---------------- fused attention: per (bh, 16-row q tile) ----------------
#define ATTN_SMEM (131072 + 8192 + 66048 + 128)

__global__ __launch_bounds__(256) void attn_kernel() {
    extern __shared__ int smem[];
    int* scores = smem;
    int* qs = smem + 16*SEQ;
    char* region = (char*)(qs + 16*HD);
    int4* Kt = (int4*)region;                      // [dd][k] padded stride 129
    int2* list = (int2*)region;
    unsigned* ctx = (unsigned*)(region + 16384);
    int* tail = (int*)(region + 66048);            // rowmax[16]; cnt at tail[16]

    int t = threadIdx.x;
    int q0 = blockIdx.x * 16;
    int bh = blockIdx.y;
    const int* Qb = g_q + (size_t)bh * SEQ * HD;
    const int* Kb = g_k + (size_t)bh * SEQ * HD;
    const int* Vb = g_v + (size_t)bh * SEQ * HD;

    for (int i = t; i < 16*HD; i += 256) {
        int r = i >> 7, d = i & (HD-1);
        qs[i] = Qb[(q0 + r)*HD + d];
    }
    __syncthreads();

    int kend = q0 + 15;
    const int4* qs4 = (const int4*)qs;

    for (int kt0 = 0; kt0 <= kend; kt0 += 128) {
        int nk = min(128, kend + 1 - kt0);
        for (int i = t; i < nk*32; i += 256) {
            int row = i >> 5, d4 = i & 31;
            int4 v = *reinterpret_cast<const int4*>(&Kb[(kt0 + row)*HD + d4*4]);
            Kt[d4*129 + row] = v;
        }
        __syncthreads();

        int k2 = (t & 63) * 2;
        int rg = t >> 6;
        if (k2 < nk) {
            unsigned acc[4][2];
#pragma unroll
            for (int i = 0; i < 4; i++) { acc[i][0] = 0u; acc[i][1] = 0u; }
#pragma unroll 8
            for (int dd = 0; dd < 32; dd++) {
                int4 kv0 = Kt[dd*129 + k2];
                int4 kv1 = Kt[dd*129 + k2 + 1];
#pragma unroll
                for (int i = 0; i < 4; i++) {
                    int r = rg + i*4;
                    int4 qv = qs4[r*32 + dd];
                    acc[i][0] += (unsigned)qv.x*(unsigned)kv0.x + (unsigned)qv.y*(unsigned)kv0.y
                               + (unsigned)qv.z*(unsigned)kv0.z + (unsigned)qv.w*(unsigned)kv0.w;
                    acc[i][1] += (unsigned)qv.x*(unsigned)kv1.x + (unsigned)qv.y*(unsigned)kv1.y
                               + (unsigned)qv.z*(unsigned)kv1.z + (unsigned)qv.w*(unsigned)kv1.w;
                }
            }
#pragma unroll
            for (int i = 0; i < 4; i++) {
                int r = rg + i*4;
                scores[r*SEQ + kt0 + k2]     = ((int)acc[i][0]) >> 1;
                scores[r*SEQ + kt0 + k2 + 1] = ((int)acc[i][1]) >> 1;
            }
        }
        __syncthreads();
    }

    // exact row max (masked entries add a -(1<<20) candidate when any exist)
    {
        int w = t >> 5, lane = t & 31;
#pragma unroll
        for (int rr = 0; rr < 2; rr++) {
            int r = w*2 + rr;
            int qr = q0 + r;
            int m = (int)0x80000000;
            for (int k = lane; k <= qr; k += 32) m = max(m, scores[r*SEQ + k]);
#pragma unroll
            for (int off = 16; off; off >>= 1) m = max(m, __shfl_xor_sync(0xffffffffu, m, off));
            if (lane == 0) {
                if (qr < SEQ - 1) m = max(m, NEGMASK);
                tail[r] = m;
            }
        }
    }
    __syncthreads();

    for (int i = t; i < 16*HD; i += 256) ctx[i] = 0u;
    int* cnt = tail + 16;
    __syncthreads();

    // sparse A*V: contributors are scores within 256 of row max
    for (int r = 0; r < 16; r++) {
        int qr = q0 + r;
        int m = tail[r];
        if (t == 0) *cnt = 0;
        __syncthreads();
        for (int k = t; k <= qr; k += 256) {
            int a = scores[r*SEQ + k] - m + 256;
            if (a > 0) {
                int pos = atomicAdd(cnt, 1);
                list[pos] = make_int2(k, a);
            }
        }
        __syncthreads();
        int c = *cnt;
        int am = NEGMASK - m + 256;
        if (t < HD) {
            unsigned sum = ctx[r*HD + t];
            for (int i = 0; i < c; i++) {
                int2 e = list[i];
                sum += (unsigned)e.y * (unsigned)Vb[e.x*HD + t];
            }
            if (qr < SEQ - 1 && am > 0) {
                for (int k = qr + 1; k < SEQ; k++)
                    sum += (unsigned)am * (unsigned)Vb[k*HD + t];
            }
            ctx[r*HD + t] = sum;
        }
        __syncthreads();
    }

    int b = bh >> 4, h = bh & (NH-1);
    for (int i = t; i < 16*HD; i += 256) {
        int r = i >> 7, d = i & (HD-1);
        int s = q0 + r;
        g_ctx[((size_t)(b*SEQ + s))*HID + h*HD + d] = ((int)ctx[i]) >> 12;
    }
}

// ---------------- output projection GEMM (int32 IMAD, exact mod 2^32) ----------------
__global__ __launch_bounds__(256) void out_gemm_kernel(float* __restrict__ out) {
    __shared__ int As[8][128];
    __shared__ int Bs[8][128];
    const signed char* W = g_w8 + (size_t)3 * HID * HID;
    const int* bias = g_b32 + 3 * HID;
    int bn = blockIdx.x;   // 0..15
    int bm = blockIdx.y;   // 0..31
    int t = threadIdx.x;
    int m0 = (t >> 4) * 8;
    int n0 = (t & 15) * 8;

    unsigned acc[8][8];
#pragma unroll
    for (int i = 0; i < 8; i++)
#pragma unroll
        for (int j = 0; j < 8; j++) acc[i][j] = 0u;

    int arow = t >> 1;
    int ak = (t & 1) * 4;
    int bkrow = t >> 5;
    int bnn = (t & 31) * 4;

    for (int kt = 0; kt < HID; kt += 8) {
        int4 av = *reinterpret_cast<const int4*>(&g_ctx[((size_t)(bm*128 + arow))*HID + kt + ak]);
        As[ak + 0][arow] = av.x;
        As[ak + 1][arow] = av.y;
        As[ak + 2][arow] = av.z;
        As[ak + 3][arow] = av.w;
        char4 wv = *reinterpret_cast<const char4*>(&W[((size_t)(kt + bkrow))*HID + bn*128 + bnn]);
        Bs[bkrow][bnn + 0] = (int)wv.x;
        Bs[bkrow][bnn + 1] = (int)wv.y;
        Bs[bkrow][bnn + 2] = (int)wv.z;
        Bs[bkrow][bnn + 3] = (int)wv.w;
        __syncthreads();
#pragma unroll
        for (int k = 0; k < 8; k++) {
            int a[8], b[8];
#pragma unroll
            for (int i = 0; i < 8; i++) a[i] = As[k][m0 + i];
#pragma unroll
            for (int j = 0; j < 8; j++) b[j] = Bs[k][n0 + j];
#pragma unroll
            for (int i = 0; i < 8; i++)
#pragma unroll
                for (int j = 0; j < 8; j++)
                    acc[i][j] += (unsigned)a[i] * (unsigned)b[j];
        }
        __syncthreads();
    }
#pragma unroll
    for (int i = 0; i < 8; i++) {
        int m = bm*128 + m0 + i;
#pragma unroll
        for (int j = 0; j < 8; j++) {
            int n = bn*128 + n0 + j;
            int val = ((int)(acc[i][j] + (unsigned)bias[n])) >> 7;
            out[(size_t)m*HID + n] = (float)val;
        }
    }
}

// ---------------- launch ----------------
extern "C" void kernel_launch(void* const* d_in, const int* in_sizes, int n_in,
                              void* d_out, int out_size) {
    const void* x  = d_in[0];
    const void* wq = d_in[1]; const void* bq = d_in[2];
    const void* wk = d_in[3]; const void* bk = d_in[4];
    const void* wv = d_in[5]; const void* bv = d_in[6];
    const void* wo = d_in[7]; const void* bo = d_in[8];
    float* out = (float*)d_out;

    detect_kernel<<<9, 256>>>(x, wq, bq, wk, bk, wv, bv, wo, bo);

    conv_x_kernel<<<(MTOT*(HID/4) + 255)/256, 256>>>(x);
    int wgrid = (HID*HID/4 + 255)/256;
    conv_w_kernel<<<wgrid, 256>>>(wq, 0, 1);
    conv_w_kernel<<<wgrid, 256>>>(wk, 1, 3);
    conv_w_kernel<<<wgrid, 256>>>(wv, 2, 5);
    conv_w_kernel<<<wgrid, 256>>>(wo, 3, 7);
    conv_b_kernel<<<(HID + 255)/256, 256>>>(bq, 0, 2);
    conv_b_kernel<<<(HID + 255)/256, 256>>>(bk, 1, 4);
    conv_b_kernel<<<(HID + 255)/256, 256>>>(bv, 2, 6);
    conv_b_kernel<<<(HID + 255)/256, 256>>>(bo, 3, 8);

    int pgrid = (HID*(HID/4) + 255)/256;
    pack_w_kernel<<<pgrid, 256>>>(0);
    pack_w_kernel<<<pgrid, 256>>>(1);
    pack_w_kernel<<<pgrid, 256>>>(2);

    dim3 pg(16, 32);
    proj_gemm_kernel<<<pg, 256>>>(0);
    proj_gemm_kernel<<<pg, 256>>>(1);
    proj_gemm_kernel<<<pg, 256>>>(2);

    cudaFuncSetAttribute(attn_kernel, cudaFuncAttributeMaxDynamicSharedMemorySize, ATTN_SMEM);
    attn_kernel<<<dim3(SEQ/16, BH), 256, ATTN_SMEM>>>();

    out_gemm_kernel<<<dim3(16, 32), 256>>>(out);
}

// round 3
// speedup vs baseline: 1.1095x; 1.1095x over previous
#include <cuda_runtime.h>
#include <cstdint>
#include <math.h>

#define SEQ 2048
#define HID 2048
#define NB  2
#define NH  16
#define HD  128
#define BH  (NB*NH)          // 32
#define MTOT (NB*SEQ)        // 4096
#define NEGMASK (-(1<<20))

// ---------------- device scratch (no allocation allowed) ----------------
__device__ int g_flag[9];                          // per-input dtype: 0=int32,1=float32,2=int8
__device__ unsigned g_x4[MTOT * (HID/4)];          // x packed u8x4   [4096][512]
__device__ signed char g_w8[4 * HID * HID];        // canonical s8 weights q,k,v,o [k][n]
__device__ int g_b32[4 * HID];                     // canonical i32 biases
__device__ unsigned g_wt[4 * HID * (HID/4)];       // w transposed+packed [n][k/4] (q,k,v,o)
__device__ int g_q[BH * SEQ * HD];                 // [bh][s][d]
__device__ int g_k[BH * SEQ * HD];
__device__ int g_v[BH * SEQ * HD];
__device__ int g_ctx[MTOT * HID];                  // [b*s][h*128+d]

// ---------------- IMMA helpers ----------------
__device__ __forceinline__ void mma_u8s8(int* d, const unsigned* a, const unsigned* b) {
    asm volatile(
        "mma.sync.aligned.m16n8k32.row.col.s32.u8.s8.s32 "
        "{%0,%1,%2,%3},{%4,%5,%6,%7},{%8,%9},{%0,%1,%2,%3};"
        : "+r"(d[0]), "+r"(d[1]), "+r"(d[2]), "+r"(d[3])
        : "r"(a[0]), "r"(a[1]), "r"(a[2]), "r"(a[3]), "r"(b[0]), "r"(b[1]));
}
__device__ __forceinline__ void ldsm_x4(unsigned* r, unsigned addr) {
    asm volatile("ldmatrix.sync.aligned.m8n8.x4.shared.b16 {%0,%1,%2,%3},[%4];"
                 : "=r"(r[0]), "=r"(r[1]), "=r"(r[2]), "=r"(r[3]) : "r"(addr));
}
__device__ __forceinline__ void ldsm_x2(unsigned* r, unsigned addr) {
    asm volatile("ldmatrix.sync.aligned.m8n8.x2.shared.b16 {%0,%1},[%2];"
                 : "=r"(r[0]), "=r"(r[1]) : "r"(addr));
}

// ---------------- dtype detection ----------------
__device__ __forceinline__ int classify_word(unsigned w) {
    if (w == 0u) return -1;
    int iv = (int)w;
    if (iv >= -520 && iv <= 520) return 0;
    float f = __int_as_float(w);
    if (isfinite(f) && fabsf(f) <= 520.0f && f != 0.0f && f == rintf(f)) return 1;
    return 2;
}

__global__ void detect_kernel(const void* p0, const void* p1, const void* p2,
                              const void* p3, const void* p4, const void* p5,
                              const void* p6, const void* p7, const void* p8) {
    const void* ptrs[9] = {p0,p1,p2,p3,p4,p5,p6,p7,p8};
    int b = blockIdx.x;
    const unsigned* w = (const unsigned*)ptrs[b];
    int n = (b == 2 || b == 4 || b == 6 || b == 8) ? 512 : 1024;
    __shared__ int votes[3];
    if (threadIdx.x < 3) votes[threadIdx.x] = 0;
    __syncthreads();
    int local[3] = {0,0,0};
    for (int i = threadIdx.x; i < n; i += blockDim.x) {
        int c = classify_word(w[i]);
        if (c >= 0) local[c]++;
    }
    for (int c = 0; c < 3; c++) if (local[c]) atomicAdd(&votes[c], local[c]);
    __syncthreads();
    if (threadIdx.x == 0) {
        int best = 0;
        if (votes[1] > votes[best]) best = 1;
        if (votes[2] > votes[best]) best = 2;
        g_flag[b] = best;
    }
}

// ---------------- canonicalize x -> u8x4 words ----------------
__global__ void conv_x_kernel(const void* __restrict__ xp) {
    int i = blockIdx.x * blockDim.x + threadIdx.x;
    if (i >= MTOT * (HID/4)) return;
    int flag = g_flag[0];
    unsigned a, b, c, d;
    if (flag == 1) {
        float4 v = reinterpret_cast<const float4*>(xp)[i];
        a = (unsigned)(int)v.x; b = (unsigned)(int)v.y;
        c = (unsigned)(int)v.z; d = (unsigned)(int)v.w;
    } else {
        int4 v = reinterpret_cast<const int4*>(xp)[i];
        a = (unsigned)v.x; b = (unsigned)v.y; c = (unsigned)v.z; d = (unsigned)v.w;
    }
    g_x4[i] = (a & 255u) | ((b & 255u) << 8) | ((c & 255u) << 16) | ((d & 255u) << 24);
}

// ---------------- canonicalize weight -> s8 [k][n] ----------------
__global__ void conv_w_kernel(const void* __restrict__ wp, int slot, int flagidx) {
    int i = blockIdx.x * blockDim.x + threadIdx.x;
    if (i >= HID * HID / 4) return;
    int flag = g_flag[flagidx];
    unsigned* dst = reinterpret_cast<unsigned*>(g_w8 + (size_t)slot * HID * HID);
    unsigned packed;
    if (flag == 2) {
        packed = reinterpret_cast<const unsigned*>(wp)[i];
    } else if (flag == 1) {
        float4 v = reinterpret_cast<const float4*>(wp)[i];
        packed = ((unsigned)(int)v.x & 255u) | (((unsigned)(int)v.y & 255u) << 8) |
                 (((unsigned)(int)v.z & 255u) << 16) | (((unsigned)(int)v.w & 255u) << 24);
    } else {
        int4 v = reinterpret_cast<const int4*>(wp)[i];
        packed = ((unsigned)v.x & 255u) | (((unsigned)v.y & 255u) << 8) |
                 (((unsigned)v.z & 255u) << 16) | (((unsigned)v.w & 255u) << 24);
    }
    dst[i] = packed;
}

// ---------------- canonicalize bias -> i32 ----------------
__global__ void conv_b_kernel(const void* __restrict__ bp, int slot, int flagidx) {
    int i = blockIdx.x * blockDim.x + threadIdx.x;
    if (i >= HID) return;
    int flag = g_flag[flagidx];
    int v;
    if (flag == 1) v = (int)reinterpret_cast<const float*>(bp)[i];
    else           v = reinterpret_cast<const int*>(bp)[i];
    g_b32[slot * HID + i] = v;
}

// ---------------- transpose+pack weight: s8 [k][n] -> wt[n][k/4] ----------------
__global__ void pack_w_kernel(int slot) {
    int i = blockIdx.x * blockDim.x + threadIdx.x;
    if (i < HID * (HID/4)) {
        const signed char* w = g_w8 + (size_t)slot * HID * HID;
        int kw = i >> 11;          // 0..511
        int n  = i & (HID-1);      // 0..2047
        unsigned b0 = (unsigned char)w[(4*kw+0)*HID + n];
        unsigned b1 = (unsigned char)w[(4*kw+1)*HID + n];
        unsigned b2 = (unsigned char)w[(4*kw+2)*HID + n];
        unsigned b3 = (unsigned char)w[(4*kw+3)*HID + n];
        g_wt[slot * (HID*(HID/4)) + n*(HID/4) + kw] = b0 | (b1<<8) | (b2<<16) | (b3<<24);
    }
}

// ---------------- QKV projection via IMMA (u8 x s8, exact) ----------------
__global__ __launch_bounds__(256) void proj_imma_kernel(int slot) {
    __shared__ unsigned char As[128*80];
    __shared__ unsigned char Bs[128*80];
    const unsigned* W4 = g_wt + slot * (HID*(HID/4));
    const int* bias = g_b32 + slot * HID;
    int* outp = (slot == 0) ? g_q : (slot == 1) ? g_k : g_v;

    int bn = blockIdx.x;   // 0..15
    int bm = blockIdx.y;   // 0..31
    int t = threadIdx.x, lane = t & 31, warp = t >> 5;
    int wm = warp >> 2, wn = warp & 3;

    unsigned aBase = (unsigned)__cvta_generic_to_shared(As);
    unsigned bBase = (unsigned)__cvta_generic_to_shared(Bs);

    int acc[4][4][4];
#pragma unroll
    for (int i = 0; i < 4; i++)
#pragma unroll
        for (int j = 0; j < 4; j++)
#pragma unroll
            for (int r = 0; r < 4; r++) acc[i][j][r] = 0;

    int lrowA = (lane & 7) + ((lane >> 3) & 1) * 8;
    int lkoffA = (lane >= 16) ? 16 : 0;
    int lrowB = (lane & 7);
    int lkoffB = ((lane >> 3) & 1) * 16;

    for (int ks = 0; ks < 32; ks++) {
        for (int idx = t; idx < 512; idx += 256) {
            int row = idx >> 2, q = idx & 3;
            int4 v = *reinterpret_cast<const int4*>(&g_x4[(size_t)(bm*128 + row)*512 + ks*16 + q*4]);
            *reinterpret_cast<int4*>(As + row*80 + q*16) = v;
            int4 w = *reinterpret_cast<const int4*>(&W4[(size_t)(bn*128 + row)*512 + ks*16 + q*4]);
            *reinterpret_cast<int4*>(Bs + row*80 + q*16) = w;
        }
        __syncthreads();
#pragma unroll
        for (int kk = 0; kk < 2; kk++) {
            unsigned bfr[4][2];
#pragma unroll
            for (int nf = 0; nf < 4; nf++)
                ldsm_x2(bfr[nf], bBase + (wn*32 + nf*8 + lrowB)*80 + kk*32 + lkoffB);
            unsigned afr[4][4];
#pragma unroll
            for (int mf = 0; mf < 4; mf++)
                ldsm_x4(afr[mf], aBase + (wm*64 + mf*16 + lrowA)*80 + kk*32 + lkoffA);
#pragma unroll
            for (int mf = 0; mf < 4; mf++)
#pragma unroll
                for (int nf = 0; nf < 4; nf++)
                    mma_u8s8(acc[mf][nf], afr[mf], bfr[nf]);
        }
        __syncthreads();
    }

#pragma unroll
    for (int mf = 0; mf < 4; mf++) {
#pragma unroll
        for (int nf = 0; nf < 4; nf++) {
            int n = bn*128 + wn*32 + nf*8 + 2*(lane & 3);
            int h = n >> 7, d = n & (HD-1);
            int bia0 = bias[n], bia1 = bias[n+1];
#pragma unroll
            for (int half = 0; half < 2; half++) {
                int r = bm*128 + wm*64 + mf*16 + (lane >> 2) + half*8;
                int b = r >> 11, s = r & (SEQ-1);
                int v0 = (acc[mf][nf][half*2+0] + bia0) >> 6;
                int v1 = (acc[mf][nf][half*2+1] + bia1) >> 6;
                *reinterpret_cast<int2*>(&outp[((size_t)(b*NH + h)*SEQ + s)*HD + d]) = make_int2(v0, v1);
            }
        }
    }
}

// ---------------- fused attention: per (bh, 16-row q tile) ----------------
#define ATTN_SMEM (131072 + 8192 + 66048 + 128)

__global__ __launch_bounds__(256) void attn_kernel() {
    extern __shared__ int smem[];
    int* scores = smem;
    int* qs = smem + 16*SEQ;
    char* region = (char*)(qs + 16*HD);
    int4* Kt = (int4*)region;
    int2* list = (int2*)region;
    unsigned* ctx = (unsigned*)(region + 16384);
    int* tail = (int*)(region + 66048);

    int t = threadIdx.x;
    int q0 = blockIdx.x * 16;
    int bh = blockIdx.y;
    const int* Qb = g_q + (size_t)bh * SEQ * HD;
    const int* Kb = g_k + (size_t)bh * SEQ * HD;
    const int* Vb = g_v + (size_t)bh * SEQ * HD;

    for (int i = t; i < 16*HD; i += 256) {
        int r = i >> 7, d = i & (HD-1);
        qs[i] = Qb[(q0 + r)*HD + d];
    }
    __syncthreads();

    int kend = q0 + 15;
    const int4* qs4 = (const int4*)qs;

    for (int kt0 = 0; kt0 <= kend; kt0 += 128) {
        int nk = min(128, kend + 1 - kt0);
        for (int i = t; i < nk*32; i += 256) {
            int row = i >> 5, d4 = i & 31;
            int4 v = *reinterpret_cast<const int4*>(&Kb[(kt0 + row)*HD + d4*4]);
            Kt[d4*129 + row] = v;
        }
        __syncthreads();

        int k2 = (t & 63) * 2;
        int rg = t >> 6;
        if (k2 < nk) {
            unsigned acc[4][2];
#pragma unroll
            for (int i = 0; i < 4; i++) { acc[i][0] = 0u; acc[i][1] = 0u; }
#pragma unroll 8
            for (int dd = 0; dd < 32; dd++) {
                int4 kv0 = Kt[dd*129 + k2];
                int4 kv1 = Kt[dd*129 + k2 + 1];
#pragma unroll
                for (int i = 0; i < 4; i++) {
                    int r = rg + i*4;
                    int4 qv = qs4[r*32 + dd];
                    acc[i][0] += (unsigned)qv.x*(unsigned)kv0.x + (unsigned)qv.y*(unsigned)kv0.y
                               + (unsigned)qv.z*(unsigned)kv0.z + (unsigned)qv.w*(unsigned)kv0.w;
                    acc[i][1] += (unsigned)qv.x*(unsigned)kv1.x + (unsigned)qv.y*(unsigned)kv1.y
                               + (unsigned)qv.z*(unsigned)kv1.z + (unsigned)qv.w*(unsigned)kv1.w;
                }
            }
#pragma unroll
            for (int i = 0; i < 4; i++) {
                int r = rg + i*4;
                scores[r*SEQ + kt0 + k2]     = ((int)acc[i][0]) >> 1;
                scores[r*SEQ + kt0 + k2 + 1] = ((int)acc[i][1]) >> 1;
            }
        }
        __syncthreads();
    }

    {
        int w = t >> 5, lane = t & 31;
#pragma unroll
        for (int rr = 0; rr < 2; rr++) {
            int r = w*2 + rr;
            int qr = q0 + r;
            int m = (int)0x80000000;
            for (int k = lane; k <= qr; k += 32) m = max(m, scores[r*SEQ + k]);
#pragma unroll
            for (int off = 16; off; off >>= 1) m = max(m, __shfl_xor_sync(0xffffffffu, m, off));
            if (lane == 0) {
                if (qr < SEQ - 1) m = max(m, NEGMASK);
                tail[r] = m;
            }
        }
    }
    __syncthreads();

    for (int i = t; i < 16*HD; i += 256) ctx[i] = 0u;
    int* cnt = tail + 16;
    __syncthreads();

    for (int r = 0; r < 16; r++) {
        int qr = q0 + r;
        int m = tail[r];
        if (t == 0) *cnt = 0;
        __syncthreads();
        for (int k = t; k <= qr; k += 256) {
            int a = scores[r*SEQ + k] - m + 256;
            if (a > 0) {
                int pos = atomicAdd(cnt, 1);
                list[pos] = make_int2(k, a);
            }
        }
        __syncthreads();
        int c = *cnt;
        int am = NEGMASK - m + 256;
        if (t < HD) {
            unsigned sum = ctx[r*HD + t];
            for (int i = 0; i < c; i++) {
                int2 e = list[i];
                sum += (unsigned)e.y * (unsigned)Vb[e.x*HD + t];
            }
            if (qr < SEQ - 1 && am > 0) {
                for (int k = qr + 1; k < SEQ; k++)
                    sum += (unsigned)am * (unsigned)Vb[k*HD + t];
            }
            ctx[r*HD + t] = sum;
        }
        __syncthreads();
    }

    int b = bh >> 4, h = bh & (NH-1);
    for (int i = t; i < 16*HD; i += 256) {
        int r = i >> 7, d = i & (HD-1);
        int s = q0 + r;
        g_ctx[((size_t)(b*SEQ + s))*HID + h*HD + d] = ((int)ctx[i]) >> 12;
    }
}

// ---------------- output projection via IMMA limbs (exact mod 2^32) ----------------
__global__ __launch_bounds__(256) void out_imma_kernel(float* __restrict__ out) {
    __shared__ unsigned char Ap[4][64*48];
    __shared__ unsigned char Bs[64*48];
    const unsigned* W4 = g_wt + 3 * (HID*(HID/4));
    const int* bias = g_b32 + 3 * HID;

    int bn = blockIdx.x;   // 0..31
    int bm = blockIdx.y;   // 0..63
    int t = threadIdx.x, lane = t & 31, warp = t >> 5;
    int wm = warp >> 2, wn = warp & 3;

    unsigned aBase[4], bBase;
#pragma unroll
    for (int l = 0; l < 4; l++) aBase[l] = (unsigned)__cvta_generic_to_shared(Ap[l]);
    bBase = (unsigned)__cvta_generic_to_shared(Bs);

    int acc[2][2][4][4];
#pragma unroll
    for (int i = 0; i < 2; i++)
#pragma unroll
        for (int j = 0; j < 2; j++)
#pragma unroll
            for (int l = 0; l < 4; l++)
#pragma unroll
                for (int r = 0; r < 4; r++) acc[i][j][l][r] = 0;

    int lrowA = (lane & 7) + ((lane >> 3) & 1) * 8;
    int lkoffA = (lane >= 16) ? 16 : 0;
    int lrowB = (lane & 7);
    int lkoffB = ((lane >> 3) & 1) * 16;

    for (int ks = 0; ks < 64; ks++) {
        for (int idx = t; idx < 512; idx += 256) {
            int row = idx >> 3, q = idx & 7;
            int4 v = *reinterpret_cast<const int4*>(&g_ctx[((size_t)(bm*64 + row))*HID + ks*32 + q*4]);
#pragma unroll
            for (int l = 0; l < 4; l++) {
                unsigned sel = (unsigned)l | ((unsigned)(l+4) << 4);
                unsigned t0 = __byte_perm((unsigned)v.x, (unsigned)v.y, sel);
                unsigned t1 = __byte_perm((unsigned)v.z, (unsigned)v.w, sel);
                *reinterpret_cast<unsigned*>(Ap[l] + row*48 + q*4) = __byte_perm(t0, t1, 0x5410);
            }
        }
        for (int idx = t; idx < 128; idx += 256) {
            int row = idx >> 1, q = idx & 1;
            int4 w = *reinterpret_cast<const int4*>(&W4[(size_t)(bn*64 + row)*512 + ks*8 + q*4]);
            *reinterpret_cast<int4*>(Bs + row*48 + q*16) = w;
        }
        __syncthreads();

        unsigned bfr[2][2];
#pragma unroll
        for (int nf = 0; nf < 2; nf++)
            ldsm_x2(bfr[nf], bBase + (wn*16 + nf*8 + lrowB)*48 + lkoffB);
#pragma unroll
        for (int mf = 0; mf < 2; mf++) {
#pragma unroll
            for (int l = 0; l < 4; l++) {
                unsigned afr[4];
                ldsm_x4(afr, aBase[l] + (wm*32 + mf*16 + lrowA)*48 + lkoffA);
#pragma unroll
                for (int nf = 0; nf < 2; nf++)
                    mma_u8s8(acc[mf][nf][l], afr, bfr[nf]);
            }
        }
        __syncthreads();
    }

#pragma unroll
    for (int mf = 0; mf < 2; mf++) {
#pragma unroll
        for (int nf = 0; nf < 2; nf++) {
            int n = bn*64 + wn*16 + nf*8 + 2*(lane & 3);
            unsigned bia0 = (unsigned)bias[n], bia1 = (unsigned)bias[n+1];
#pragma unroll
            for (int half = 0; half < 2; half++) {
                int r = bm*64 + wm*32 + mf*16 + (lane >> 2) + half*8;
                unsigned u0 = (unsigned)acc[mf][nf][0][half*2+0]
                            + ((unsigned)acc[mf][nf][1][half*2+0] << 8)
                            + ((unsigned)acc[mf][nf][2][half*2+0] << 16)
                            + ((unsigned)acc[mf][nf][3][half*2+0] << 24) + bia0;
                unsigned u1 = (unsigned)acc[mf][nf][0][half*2+1]
                            + ((unsigned)acc[mf][nf][1][half*2+1] << 8)
                            + ((unsigned)acc[mf][nf][2][half*2+1] << 16)
                            + ((unsigned)acc[mf][nf][3][half*2+1] << 24) + bia1;
                float2 fv = make_float2((float)(((int)u0) >> 7), (float)(((int)u1) >> 7));
                *reinterpret_cast<float2*>(&out[(size_t)r*HID + n]) = fv;
            }
        }
    }
}

// ---------------- launch ----------------
extern "C" void kernel_launch(void* const* d_in, const int* in_sizes, int n_in,
                              void* d_out, int out_size) {
    const void* x  = d_in[0];
    const void* wq = d_in[1]; const void* bq = d_in[2];
    const void* wk = d_in[3]; const void* bk = d_in[4];
    const void* wv = d_in[5]; const void* bv = d_in[6];
    const void* wo = d_in[7]; const void* bo = d_in[8];
    float* out = (float*)d_out;

    detect_kernel<<<9, 256>>>(x, wq, bq, wk, bk, wv, bv, wo, bo);

    conv_x_kernel<<<(MTOT*(HID/4) + 255)/256, 256>>>(x);
    int wgrid = (HID*HID/4 + 255)/256;
    conv_w_kernel<<<wgrid, 256>>>(wq, 0, 1);
    conv_w_kernel<<<wgrid, 256>>>(wk, 1, 3);
    conv_w_kernel<<<wgrid, 256>>>(wv, 2, 5);
    conv_w_kernel<<<wgrid, 256>>>(wo, 3, 7);
    conv_b_kernel<<<(HID + 255)/256, 256>>>(bq, 0, 2);
    conv_b_kernel<<<(HID + 255)/256, 256>>>(bk, 1, 4);
    conv_b_kernel<<<(HID + 255)/256, 256>>>(bv, 2, 6);
    conv_b_kernel<<<(HID + 255)/256, 256>>>(bo, 3, 8);

    int pgrid = (HID*(HID/4) + 255)/256;
    pack_w_kernel<<<pgrid, 256>>>(0);
    pack_w_kernel<<<pgrid, 256>>>(1);
    pack_w_kernel<<<pgrid, 256>>>(2);
    pack_w_kernel<<<pgrid, 256>>>(3);

    dim3 pg(16, 32);
    proj_imma_kernel<<<pg, 256>>>(0);
    proj_imma_kernel<<<pg, 256>>>(1);
    proj_imma_kernel<<<pg, 256>>>(2);

    cudaFuncSetAttribute(attn_kernel, cudaFuncAttributeMaxDynamicSharedMemorySize, ATTN_SMEM);
    attn_kernel<<<dim3(SEQ/16, BH), 256, ATTN_SMEM>>>();

    out_imma_kernel<<<dim3(32, 64), 256>>>(out);
}